// round 13
// baseline (speedup 1.0000x reference)
#include <cuda_runtime.h>
#include <cuda_fp16.h>

// ============================================================================
// CfC Liquid Neural Network, B=256, T=1024. Round 12.
//  - fp16 weights (fp32 z / fp32 acc), half2(k,k+1) [k2][u] tiles; FFMA2.
//  - 128 CTAs x 512 threads, 2 batch rows per CTA, 1024-step recurrence.
//  - NEW: W split into W_in / W_rec per cell. Phase A = cell0 (L2-streamed)
//    + W1_rec*h1 + W2_rec*h2 (smem) concurrently; Phase B = W1_in*h0 only;
//    Phase C = W2_in*h1 only. Recurrent work hides under cell0's stream.
//  - cell1/cell2 weights smem-resident; fast MUFU activations; fc hoisted.
// ============================================================================

#define F0 128
#define U0 135
#define C0 263
#define CP0 264
#define UP0 136
#define U1 89
#define C1 224
#define UP1 92
#define U2 32
#define C2 121
#define UP2 32

// packed matrices (halves)
#define W0_MAT   (CP0*UP0)          // 35904
#define W1I_MAT  (136*UP1)          // 12512
#define W1R_MAT  (96*UP1)           // 8832
#define W2I_MAT  (96*UP2)           // 3072
#define W2R_MAT  (32*UP2)           // 1024

#define OFF_W0    0
#define OFF_W1I   (3*W0_MAT)                 // 107712
#define OFF_W1R   (OFF_W1I + 3*W1I_MAT)      // 145248
#define OFF_W2I   (OFF_W1R + 3*W1R_MAT)      // 171744
#define OFF_W2R   (OFF_W2I + 3*W2I_MAT)      // 180960
#define TOT_W     (OFF_W2R + 3*W2R_MAT)      // 184032

#define OFF_B0 0
#define OFF_B1 (3*UP0)              // 408
#define OFF_B2 (OFF_B1 + 3*UP1)     // 684
#define TOT_B  (OFF_B2 + 3*UP2)     // 780

// uint4 counts per mat
#define W0_V4   (W0_MAT/8)          // 4488
#define W1I_V4  (W1I_MAT/8)         // 1564
#define W1R_V4  (W1R_MAT/8)         // 1104
#define W2I_V4  (W2I_MAT/8)         // 384
#define W2R_V4  (W2R_MAT/8)         // 128

__device__ __align__(16) __half g_wh[TOT_W];
__device__ float g_b[TOT_B];

// ---- packed fp32x2 FMA: d = a*b + d ----
__device__ __forceinline__ void fma2(float2& d, const float2& a, const float2& b)
{
    unsigned long long& dv = reinterpret_cast<unsigned long long&>(d);
    asm("fma.rn.f32x2 %0, %1, %2, %0;"
        : "+l"(dv)
        : "l"(reinterpret_cast<const unsigned long long&>(a)),
          "l"(reinterpret_cast<const unsigned long long&>(b)));
}

// ---- fast activations ----
__device__ __forceinline__ float fast_tanh(float x)
{
    float e = __expf(2.f * x);
    return 1.f - __fdividef(2.f, e + 1.f);
}
__device__ __forceinline__ float fast_sigmoid(float x)
{
    return __fdividef(1.f, 1.f + __expf(-x));
}

// ---- Generic pack: mat half idx = (k2*UP + u)*2 + r, src col = COFF + k ----
template<int CSRC, int COFF, int CVALID, int CP, int U, int UP>
__global__ void pack_kernel(int woff, int boff,
    const float* __restrict__ ff1w, const float* __restrict__ ff1b,
    const float* __restrict__ ff2w, const float* __restrict__ ff2b,
    const float* __restrict__ taw,  const float* __restrict__ tab,
    const float* __restrict__ tbw,  const float* __restrict__ tbb,
    const int*   __restrict__ mask)
{
    const int per = CP * UP;
    const int n = 3 * per;
    for (int idx = blockIdx.x * blockDim.x + threadIdx.x; idx < n;
         idx += gridDim.x * blockDim.x) {
        int mat = idx / per;
        int e = idx - mat * per;
        int rbit = e & 1;
        int t1 = e >> 1;
        int u = t1 % UP;
        int k2 = t1 / UP;
        int k = 2 * k2 + rbit;
        float v = 0.f;
        if (k < CVALID && u < U) {
            int src = u * CSRC + COFF + k;
            if (mat == 0)      v = ff1w[src] * (float)mask[src];
            else if (mat == 1) v = ff2w[src] * (float)mask[src];
            else               v = taw[src] + tbw[src];
        }
        g_wh[woff + idx] = __float2half_rn(v);
    }
    if (boff >= 0) {
        for (int idx = blockIdx.x * blockDim.x + threadIdx.x; idx < 3 * UP;
             idx += gridDim.x * blockDim.x) {
            int mat = idx / UP;
            int u = idx - mat * UP;
            float v = 0.f;
            if (u < U) v = (mat == 0) ? ff1b[u] : (mat == 1 ? ff2b[u] : (tab[u] + tbb[u]));
            g_b[boff + idx] = v;
        }
    }
}

// ---- Dot task: 4 units x 2 rows over k4 range [kb, ke); float2 acc over k ----
template<int UP>
__device__ __forceinline__ void dot2(
    const uint4* __restrict__ wbase,
    const float4* __restrict__ za, const float4* __restrict__ zb,
    int ub, int kb, int ke, float2 acc[8])
{
    const uint4* wp = wbase + (size_t)(2 * kb) * (UP / 4) + ub;
#pragma unroll 4
    for (int k4 = kb; k4 < ke; ++k4) {
        uint4 wa = wp[0];
        uint4 wc = wp[UP / 4];
        wp += UP / 2;
        float4 va = za[k4];
        float4 vb = zb[k4];
        float2 a01 = make_float2(va.x, va.y), a23 = make_float2(va.z, va.w);
        float2 b01 = make_float2(vb.x, vb.y), b23 = make_float2(vb.z, vb.w);
        float2 w;
        w = __half22float2(*(const __half2*)&wa.x);
        fma2(acc[0], w, a01); fma2(acc[1], w, b01);
        w = __half22float2(*(const __half2*)&wa.y);
        fma2(acc[2], w, a01); fma2(acc[3], w, b01);
        w = __half22float2(*(const __half2*)&wa.z);
        fma2(acc[4], w, a01); fma2(acc[5], w, b01);
        w = __half22float2(*(const __half2*)&wa.w);
        fma2(acc[6], w, a01); fma2(acc[7], w, b01);
        w = __half22float2(*(const __half2*)&wc.x);
        fma2(acc[0], w, a23); fma2(acc[1], w, b23);
        w = __half22float2(*(const __half2*)&wc.y);
        fma2(acc[2], w, a23); fma2(acc[3], w, b23);
        w = __half22float2(*(const __half2*)&wc.z);
        fma2(acc[4], w, a23); fma2(acc[5], w, b23);
        w = __half22float2(*(const __half2*)&wc.w);
        fma2(acc[6], w, a23); fma2(acc[7], w, b23);
    }
}

// ---- smem layout (byte offsets; all multiples of 16) ----
#define SB_W1I  0                            // 75072 B
#define SB_W1R  (SB_W1I + 3*W1I_MAT*2)       // 75072
#define SB_W2I  (SB_W1R + 3*W1R_MAT*2)       // 128064
#define SB_W2R  (SB_W2I + 3*W2I_MAT*2)       // 146496
#define SB_B    (SB_W2R + 3*W2R_MAT*2)       // 152640
#define SB_Z0   (SB_B + TOT_B*4)             // 155760
#define SB_H1R  (SB_Z0 + 2*CP0*4)            // 157872
#define SB_H2   (SB_H1R + 2*96*4)            // 158640
#define SB_A0   (SB_H2 + 2*32*4)             // 158896
#define SB_A1   (SB_A0 + 3*4*2*UP0*4)        // 171952
#define SB_A2   (SB_A1 + 3*2*UP1*4)          // 174160
#define SB_AB   (SB_A2 + 3*2*UP2*4)          // 174928
#define SB_AC   (SB_AB + 3*7*2*UP1*4)        // 190384
#define SB_TOT  (SB_AC + 3*16*2*UP2*4)       // 202672 B

#define KS0 4
#define KSB 7
#define KSC 16

__global__ __launch_bounds__(512, 1)
void lnn_main(const float* __restrict__ x, float* __restrict__ out)
{
    extern __shared__ __align__(16) char smraw[];
    float*  sb   = (float*)(smraw + SB_B);
    float*  z0   = (float*)(smraw + SB_Z0);
    float*  h1r  = (float*)(smraw + SB_H1R);
    float*  h2   = (float*)(smraw + SB_H2);
    float*  actA0 = (float*)(smraw + SB_A0);
    float*  actA1 = (float*)(smraw + SB_A1);
    float*  actA2 = (float*)(smraw + SB_A2);
    float*  actB  = (float*)(smraw + SB_AB);
    float*  actC  = (float*)(smraw + SB_AC);
    const uint4* sW1i = (const uint4*)(smraw + SB_W1I);
    const uint4* sW1r = (const uint4*)(smraw + SB_W1R);
    const uint4* sW2i = (const uint4*)(smraw + SB_W2I);
    const uint4* sW2r = (const uint4*)(smraw + SB_W2R);
    const uint4* gw0  = (const uint4*)g_wh;       // OFF_W0 == 0
    float4* z0v  = (float4*)z0;
    const float4* h1rv = (const float4*)h1r;
    const float4* h2v  = (const float4*)h2;

    const int tid = threadIdx.x;

    // Fill smem caches
    {
        const uint4* gsrc = (const uint4*)g_wh;
        uint4* d = (uint4*)smraw;   // W sections are contiguous from SB_W1I=0
        const int total = 3 * (W1I_V4 + W1R_V4 + W2I_V4 + W2R_V4);  // 9540
        for (int i = tid; i < total; i += 512) d[i] = gsrc[OFF_W1I / 8 + i];
    }
    for (int i = tid; i < TOT_B; i += 512) sb[i] = g_b[i];
    for (int i = tid; i < 2 * CP0; i += 512) z0[i] = 0.f;
    for (int i = tid; i < 2 * 96; i += 512) h1r[i] = 0.f;
    for (int i = tid; i < 2 * 32; i += 512) h2[i] = 0.f;
    __syncthreads();

    const int b0 = blockIdx.x * 2;
    const float4* xv = (const float4*)x + (size_t)b0 * 1024 * 32;
    const int xr = (tid - 448) >> 5, xi = (tid - 448) & 31;

    float4 xreg = make_float4(0.f, 0.f, 0.f, 0.f);
    if (tid >= 448)
        z0v[xr * (CP0 / 4) + xi] = xv[((size_t)xr * 1024 + 0) * 32 + xi];
    __syncthreads();
    if (tid >= 448) xreg = xv[((size_t)xr * 1024 + 1) * 32 + xi];

    for (int t = 0; t < 1024; ++t) {
        // ================= Phase A: cell0 full + W1_rec*h1 + W2_rec*h2 ======
        if (tid < 69) {
            // W1_rec: 3 mats x 23 ublk (24 k4 each), bias folded in
            int ub = tid % 23, mat = tid / 23;
            int u0 = 4 * ub;
            float2 acc[8];
#pragma unroll
            for (int u = 0; u < 4; ++u) {
                float bv = sb[OFF_B1 + mat * UP1 + u0 + u];
                acc[2 * u]     = make_float2(bv, 0.f);
                acc[2 * u + 1] = make_float2(bv, 0.f);
            }
            dot2<UP1>(sW1r + mat * W1R_V4, h1rv, h1rv + 24, ub, 0, 24, acc);
            float* ap = actA1 + (mat * 2) * UP1 + u0;
            *(float4*)ap         = make_float4(acc[0].x + acc[0].y, acc[2].x + acc[2].y,
                                               acc[4].x + acc[4].y, acc[6].x + acc[6].y);
            *(float4*)(ap + UP1) = make_float4(acc[1].x + acc[1].y, acc[3].x + acc[3].y,
                                               acc[5].x + acc[5].y, acc[7].x + acc[7].y);
        } else if (tid < 93) {
            // W2_rec: 3 mats x 8 ublk (8 k4 each), bias folded in
            int i = tid - 69;
            int ub = i % 8, mat = i / 8;
            int u0 = 4 * ub;
            float2 acc[8];
#pragma unroll
            for (int u = 0; u < 4; ++u) {
                float bv = sb[OFF_B2 + mat * UP2 + u0 + u];
                acc[2 * u]     = make_float2(bv, 0.f);
                acc[2 * u + 1] = make_float2(bv, 0.f);
            }
            dot2<UP2>(sW2r + mat * W2R_V4, h2v, h2v + 8, ub, 0, 8, acc);
            float* ap = actA2 + (mat * 2) * UP2 + u0;
            *(float4*)ap         = make_float4(acc[0].x + acc[0].y, acc[2].x + acc[2].y,
                                               acc[4].x + acc[4].y, acc[6].x + acc[6].y);
            *(float4*)(ap + UP2) = make_float4(acc[1].x + acc[1].y, acc[3].x + acc[3].y,
                                               acc[5].x + acc[5].y, acc[7].x + acc[7].y);
        } else if (tid >= 104) {
            // cell0: 3 mats x 34 ublk x 4 ks = 408 tasks (L2-streamed)
            int i = tid - 104;
            int ub = i % 34, q = i / 34;
            int ks = q & 3, mat = q >> 2;
            int u0 = 4 * ub;
            float2 acc[8];
#pragma unroll
            for (int u = 0; u < 4; ++u) {
                float bv = (ks == 0) ? sb[OFF_B0 + mat * UP0 + u0 + u] : 0.f;
                acc[2 * u]     = make_float2(bv, 0.f);
                acc[2 * u + 1] = make_float2(bv, 0.f);
            }
            int kb = (ks * 66) >> 2, ke = ((ks + 1) * 66) >> 2;
            dot2<UP0>(gw0 + mat * W0_V4, z0v, z0v + 66, ub, kb, ke, acc);
            float* ap = actA0 + ((mat * KS0 + ks) * 2) * UP0 + u0;
            *(float4*)ap         = make_float4(acc[0].x + acc[0].y, acc[2].x + acc[2].y,
                                               acc[4].x + acc[4].y, acc[6].x + acc[6].y);
            *(float4*)(ap + UP0) = make_float4(acc[1].x + acc[1].y, acc[3].x + acc[3].y,
                                               acc[5].x + acc[5].y, acc[7].x + acc[7].y);
        }
        __syncthreads();

        // ================= epi0 (270 thr) + x_{t+1} store (448+) ============
        if (tid < 270) {
            int u = tid >> 1, r = tid & 1;
            float f1 = 0.f, f2 = 0.f, tt = 0.f;
#pragma unroll
            for (int ks = 0; ks < KS0; ++ks) {
                f1 += actA0[((0 * KS0 + ks) * 2 + r) * UP0 + u];
                f2 += actA0[((1 * KS0 + ks) * 2 + r) * UP0 + u];
                tt += actA0[((2 * KS0 + ks) * 2 + r) * UP0 + u];
            }
            f1 = fast_tanh(f1); f2 = fast_tanh(f2);
            float s = fast_sigmoid(tt);
            float h = f1 + s * (f2 - f1);
            z0[r * CP0 + F0 + u] = h;      // h0 (phase B reads from here too)
        } else if (tid >= 448) {
            z0v[xr * (CP0 / 4) + xi] = xreg;
        }
        __syncthreads();
        if (tid >= 448) {
            int tn = (t + 2 < 1024) ? t + 2 : 1023;
            xreg = xv[((size_t)xr * 1024 + tn) * 32 + xi];
        }

        // ================= Phase B: W1_in * h0 (smem) =======================
        if (tid < 483) {
            int ub = tid % 23, q = tid / 23;
            int ks = q % KSB, mat = q / KSB;
            int u0 = 4 * ub;
            float2 acc[8];
#pragma unroll
            for (int i = 0; i < 8; ++i) acc[i] = make_float2(0.f, 0.f);
            int kb = (ks * 34) / KSB, ke = ((ks + 1) * 34) / KSB;
            // h0 lives in z0 cols 128..263 (float4-aligned at idx 32)
            dot2<UP1>(sW1i + mat * W1I_V4, z0v + 32, z0v + 98, ub, kb, ke, acc);
            float* ap = actB + ((mat * KSB + ks) * 2) * UP1 + u0;
            *(float4*)ap         = make_float4(acc[0].x + acc[0].y, acc[2].x + acc[2].y,
                                               acc[4].x + acc[4].y, acc[6].x + acc[6].y);
            *(float4*)(ap + UP1) = make_float4(acc[1].x + acc[1].y, acc[3].x + acc[3].y,
                                               acc[5].x + acc[5].y, acc[7].x + acc[7].y);
        }
        __syncthreads();

        // ================= epi1 (178 thr): combine A-rec + B ================
        if (tid < 178) {
            int u = tid >> 1, r = tid & 1;
            float f1 = actA1[(0 * 2 + r) * UP1 + u];
            float f2 = actA1[(1 * 2 + r) * UP1 + u];
            float tt = actA1[(2 * 2 + r) * UP1 + u];
#pragma unroll
            for (int ks = 0; ks < KSB; ++ks) {
                f1 += actB[((0 * KSB + ks) * 2 + r) * UP1 + u];
                f2 += actB[((1 * KSB + ks) * 2 + r) * UP1 + u];
                tt += actB[((2 * KSB + ks) * 2 + r) * UP1 + u];
            }
            f1 = fast_tanh(f1); f2 = fast_tanh(f2);
            float s = fast_sigmoid(tt);
            float h = f1 + s * (f2 - f1);
            h1r[r * 96 + u] = h;           // next-step phase A + phase C input
        }
        __syncthreads();

        // ================= Phase C: W2_in * h1 (smem) =======================
        if (tid < 384) {
            int ub = tid & 7, q = tid >> 3;
            int ks = q & 15, mat = q >> 4;
            int u0 = 4 * ub;
            float2 acc[8];
#pragma unroll
            for (int i = 0; i < 8; ++i) acc[i] = make_float2(0.f, 0.f);
            int kb = (ks * 24) >> 4, ke = ((ks + 1) * 24) >> 4;
            dot2<UP2>(sW2i + mat * W2I_V4, h1rv, h1rv + 24, ub, kb, ke, acc);
            float* ap = actC + ((mat * KSC + ks) * 2) * UP2 + u0;
            *(float4*)ap         = make_float4(acc[0].x + acc[0].y, acc[2].x + acc[2].y,
                                               acc[4].x + acc[4].y, acc[6].x + acc[6].y);
            *(float4*)(ap + UP2) = make_float4(acc[1].x + acc[1].y, acc[3].x + acc[3].y,
                                               acc[5].x + acc[5].y, acc[7].x + acc[7].y);
        }
        __syncthreads();

        // ================= epi2 (64 thr): combine A-rec + C, write out ======
        if (tid < 64) {
            int u = tid >> 1, r = tid & 1;
            float f1 = actA2[(0 * 2 + r) * UP2 + u];
            float f2 = actA2[(1 * 2 + r) * UP2 + u];
            float tt = actA2[(2 * 2 + r) * UP2 + u];
#pragma unroll
            for (int ks = 0; ks < KSC; ++ks) {
                f1 += actC[((0 * KSC + ks) * 2 + r) * UP2 + u];
                f2 += actC[((1 * KSC + ks) * 2 + r) * UP2 + u];
                tt += actC[((2 * KSC + ks) * 2 + r) * UP2 + u];
            }
            f1 = fast_tanh(f1); f2 = fast_tanh(f2);
            float s = fast_sigmoid(tt);
            float h = f1 + s * (f2 - f1);
            h2[r * 32 + u] = h;
            out[(((size_t)(b0 + r)) * 1024 + t) * 32 + u] = h;
        }
        __syncthreads();
    }
}

// ---- fc head applied in place over out[256*1024][32] ----
__global__ __launch_bounds__(256)
void fc_kernel(float* __restrict__ out, const float* __restrict__ fcw,
               const float* __restrict__ fcb)
{
    __shared__ float w[1024];
    __shared__ float b[32];
    int tid = threadIdx.x;
    for (int i = tid; i < 1024; i += 256) w[i] = fcw[i];
    if (tid < 32) b[tid] = fcb[tid];
    __syncthreads();

    size_t pos = (size_t)blockIdx.x * 256 + tid;
    float4* p = reinterpret_cast<float4*>(out) + pos * 8;
    float h[32];
    float4 v[8];
#pragma unroll
    for (int i = 0; i < 8; ++i) v[i] = p[i];
#pragma unroll
    for (int i = 0; i < 8; ++i) {
        h[4 * i + 0] = v[i].x; h[4 * i + 1] = v[i].y;
        h[4 * i + 2] = v[i].z; h[4 * i + 3] = v[i].w;
    }
#pragma unroll
    for (int i = 0; i < 8; ++i) {
        float y[4];
#pragma unroll
        for (int j = 0; j < 4; ++j) {
            int o = 4 * i + j;
            float acc = b[o];
#pragma unroll
            for (int u = 0; u < 32; ++u) acc = fmaf(w[o * 32 + u], h[u], acc);
            y[j] = acc;
        }
        p[i] = make_float4(y[0], y[1], y[2], y[3]);
    }
}

// ============================================================================
extern "C" void kernel_launch(void* const* d_in, const int* in_sizes, int n_in,
                              void* d_out, int out_size)
{
    (void)n_in; (void)out_size;
    int base[3], mi[3], fwi, fbi;
    if (in_sizes[9] == U0 * C0) {          // interleaved dict order
        base[0] = 1;  mi[0] = 9;
        base[1] = 10; mi[1] = 18;
        base[2] = 19; mi[2] = 27;
        fwi = 28; fbi = 29;
    } else {                                // signature order
        base[0] = 1; base[1] = 9; base[2] = 17;
        fwi = 25; fbi = 26;
        mi[0] = 27; mi[1] = 28; mi[2] = 29;
    }

    const float* xin = (const float*)d_in[0];
    const float* fcw = (const float*)d_in[fwi];
    const float* fcb = (const float*)d_in[fbi];

#define LPTRS(l) \
    (const float*)d_in[base[l]+0], (const float*)d_in[base[l]+1], \
    (const float*)d_in[base[l]+2], (const float*)d_in[base[l]+3], \
    (const float*)d_in[base[l]+4], (const float*)d_in[base[l]+5], \
    (const float*)d_in[base[l]+6], (const float*)d_in[base[l]+7], \
    (const int*)d_in[mi[l]]

    // W0 full (also writes layer0 bias)
    pack_kernel<C0, 0, C0, CP0, U0, UP0>
        <<<(3 * W0_MAT + 255) / 256, 256>>>(OFF_W0, OFF_B0, LPTRS(0));
    // W1 input part (cols 0..134) and recurrent part (cols 135..223, + bias)
    pack_kernel<C1, 0, 135, 136, U1, UP1>
        <<<(3 * W1I_MAT + 255) / 256, 256>>>(OFF_W1I, -1, LPTRS(1));
    pack_kernel<C1, 135, 89, 96, U1, UP1>
        <<<(3 * W1R_MAT + 255) / 256, 256>>>(OFF_W1R, OFF_B1, LPTRS(1));
    // W2 input part (cols 0..88) and recurrent part (cols 89..120, + bias)
    pack_kernel<C2, 0, 89, 96, U2, UP2>
        <<<(3 * W2I_MAT + 255) / 256, 256>>>(OFF_W2I, -1, LPTRS(2));
    pack_kernel<C2, 89, 32, 32, U2, UP2>
        <<<(3 * W2R_MAT + 255) / 256, 256>>>(OFF_W2R, OFF_B2, LPTRS(2));
#undef LPTRS

    static_assert(SB_TOT <= 232448, "smem over budget");
    cudaFuncSetAttribute(lnn_main, cudaFuncAttributeMaxDynamicSharedMemorySize,
                         SB_TOT);
    lnn_main<<<128, 512, SB_TOT>>>(xin, (float*)d_out);
    fc_kernel<<<1024, 256>>>((float*)d_out, fcw, fcb);
}